// round 3
// baseline (speedup 1.0000x reference)
#include <cuda_runtime.h>
#include <math.h>

// Problem constants (fixed by setup_inputs)
#define B_  2
#define T_  8
#define M_  900
#define H_  27
#define W_  27
#define D_  1024
#define PATCH_ 14

#define NBLK (B_ * M_)                    // 1800 blocks, one per (b, m)
#define NPAIR_DENOM (B_ * (T_ - 1) * M_)  // 12600, mean denominator

__device__ float        g_partials[NBLK];
__device__ unsigned int g_done = 0;   // reset to 0 by the last block each launch

__global__ __launch_bounds__(256, 8)
void gather_l1_fused_kernel(const float* __restrict__ features,
                            const float* __restrict__ tracks,
                            const int* __restrict__ vis,   // bool stored as int32
                            float* __restrict__ out)
{
    const int bm  = blockIdx.x;          // 0..1799
    const int b   = bm / M_;
    const int m   = bm - b * M_;
    const int tid = threadIdx.x;         // 256 threads = 1024 floats / 4

    __shared__ int s_nn[T_];
    __shared__ int s_vis[T_];

    if (tid < T_) {
        const int t = tid;
        // tracks layout: [B, T, M, 2] (x, y) in pixel space
        const float* tr = tracks + (((size_t)(b * T_ + t) * M_ + m) * 2);
        float x = tr[0];
        float y = tr[1];
        // nearest patch center c_j = 14j+7  ->  j = clamp(floor(x/14), 0, 26)
        int j = (int)floorf(x * (1.0f / PATCH_));
        int i = (int)floorf(y * (1.0f / PATCH_));
        j = min(W_ - 1, max(0, j));
        i = min(H_ - 1, max(0, i));
        s_nn[t]  = i * W_ + j;
        s_vis[t] = vis[(size_t)(b * T_ + t) * M_ + m];
    }
    __syncthreads();

    // Gather 8 rows; each thread owns one float4 lane -> 8 independent LDG.128
    float4 pf[T_];
#pragma unroll
    for (int t = 0; t < T_; t++) {
        const float4* row = (const float4*)(features
            + ((size_t)(b * T_ + t) * (H_ * W_) + s_nn[t]) * D_);
        pf[t] = row[tid];
    }

    float acc = 0.0f;
#pragma unroll
    for (int t = 0; t < T_ - 1; t++) {
        float l1c = fabsf(pf[t].x - pf[t + 1].x)
                  + fabsf(pf[t].y - pf[t + 1].y)
                  + fabsf(pf[t].z - pf[t + 1].z)
                  + fabsf(pf[t].w - pf[t + 1].w);
        float l1r = fabsf(pf[0].x - pf[t + 1].x)
                  + fabsf(pf[0].y - pf[t + 1].y)
                  + fabsf(pf[0].z - pf[t + 1].z)
                  + fabsf(pf[0].w - pf[t + 1].w);
        if (s_vis[t] && s_vis[t + 1]) acc += l1c;
        if (s_vis[0] && s_vis[t + 1]) acc += l1r;
    }

    // Block reduction: warp shuffle, then 8 warp sums via shared
#pragma unroll
    for (int o = 16; o > 0; o >>= 1)
        acc += __shfl_down_sync(0xffffffffu, acc, o);

    __shared__ float s_warp[8];
    const int lane = tid & 31;
    const int wid  = tid >> 5;
    if (lane == 0) s_warp[wid] = acc;
    __syncthreads();

    __shared__ bool s_is_last;
    if (tid == 0) {
        float s = 0.0f;
#pragma unroll
        for (int w = 0; w < 8; w++) s += s_warp[w];
        g_partials[bm] = s;
        __threadfence();                       // make partial visible GPU-wide
        unsigned int prev = atomicAdd(&g_done, 1u);
        s_is_last = (prev == NBLK - 1);
    }
    __syncthreads();

    // Last block to finish reduces all partials (fixed order -> deterministic)
    if (s_is_last) {
        double dacc = 0.0;
        for (int i = tid; i < NBLK; i += 256)
            dacc += (double)g_partials[i];

#pragma unroll
        for (int o = 16; o > 0; o >>= 1)
            dacc += __shfl_down_sync(0xffffffffu, dacc, o);

        __shared__ double s_dwarp[8];
        if (lane == 0) s_dwarp[wid] = dacc;
        __syncthreads();
        if (tid == 0) {
            double s = 0.0;
#pragma unroll
            for (int w = 0; w < 8; w++) s += s_dwarp[w];
            out[0] = (float)(0.01 * s / (double)NPAIR_DENOM);
            g_done = 0;                        // reset for next graph replay
        }
    }
}

extern "C" void kernel_launch(void* const* d_in, const int* in_sizes, int n_in,
                              void* d_out, int out_size)
{
    const float* features = (const float*)d_in[0];  // [B*T, H*W, D] f32
    const float* tracks   = (const float*)d_in[1];  // [B, T, M, 2]  f32
    const int*   vis      = (const int*)d_in[2];    // [B, T, M]     bool->int32
    float*       out      = (float*)d_out;

    gather_l1_fused_kernel<<<NBLK, 256>>>(features, tracks, vis, out);
}

// round 4
// speedup vs baseline: 1.2739x; 1.2739x over previous
#include <cuda_runtime.h>
#include <math.h>

// Problem constants (fixed by setup_inputs)
#define B_  2
#define T_  8
#define M_  900
#define H_  27
#define W_  27
#define D_  1024
#define PATCH_ 14

#define NBLK (B_ * M_)                    // 1800 blocks, one per (b, m)
#define NPAIR_DENOM (B_ * (T_ - 1) * M_)  // 12600, mean denominator

__device__ float        g_partials[NBLK];
__device__ unsigned int g_done = 0;   // reset by the last block each launch

__global__ __launch_bounds__(256, 4)     // 64-reg budget: keep all 8 LDG.128 in flight
void gather_l1_fused_kernel(const float* __restrict__ features,
                            const float* __restrict__ tracks,
                            const int* __restrict__ vis,   // bool stored as int32
                            float* __restrict__ out)
{
    const int bm   = blockIdx.x;         // 0..1799
    const int b    = bm / M_;
    const int m    = bm - b * M_;
    const int tid  = threadIdx.x;        // 256 threads = 1024 floats / 4
    const int lane = tid & 31;
    const int wid  = tid >> 5;

    // --- Per-warp index computation: lanes 0..7 handle frame t=lane.
    // Addresses are identical across warps -> L1 broadcast; no block barrier.
    int my_nn = 0, my_vis = 0;
    if (lane < T_) {
        const int t = lane;
        const float2 tr = *(const float2*)(tracks
            + (((size_t)(b * T_ + t) * M_ + m) * 2));
        // nearest patch center c_j = 14j+7 -> j = clamp(floor(x/14), 0, 26)
        int j = (int)floorf(tr.x * (1.0f / PATCH_));
        int i = (int)floorf(tr.y * (1.0f / PATCH_));
        j = min(W_ - 1, max(0, j));
        i = min(H_ - 1, max(0, i));
        my_nn  = i * W_ + j;
        my_vis = vis[(size_t)(b * T_ + t) * M_ + m];
    }

    int nn[T_], vz[T_];
#pragma unroll
    for (int t = 0; t < T_; t++) {
        nn[t] = __shfl_sync(0xffffffffu, my_nn,  t);
        vz[t] = __shfl_sync(0xffffffffu, my_vis, t);
    }

    // --- Gather 8 rows; each thread owns one float4 lane -> 8 independent LDG.128
    float4 pf[T_];
#pragma unroll
    for (int t = 0; t < T_; t++) {
        const float4* row = (const float4*)(features
            + ((size_t)(b * T_ + t) * (H_ * W_) + nn[t]) * D_);
        pf[t] = row[tid];
    }

    float acc = 0.0f;
#pragma unroll
    for (int t = 0; t < T_ - 1; t++) {
        float l1c = fabsf(pf[t].x - pf[t + 1].x)
                  + fabsf(pf[t].y - pf[t + 1].y)
                  + fabsf(pf[t].z - pf[t + 1].z)
                  + fabsf(pf[t].w - pf[t + 1].w);
        float l1r = fabsf(pf[0].x - pf[t + 1].x)
                  + fabsf(pf[0].y - pf[t + 1].y)
                  + fabsf(pf[0].z - pf[t + 1].z)
                  + fabsf(pf[0].w - pf[t + 1].w);
        if (vz[t] && vz[t + 1]) acc += l1c;
        if (vz[0] && vz[t + 1]) acc += l1r;
    }

    // --- Block reduction: warp shuffle, then 8 warp sums via shared
#pragma unroll
    for (int o = 16; o > 0; o >>= 1)
        acc += __shfl_down_sync(0xffffffffu, acc, o);

    __shared__ float s_warp[8];
    if (lane == 0) s_warp[wid] = acc;
    __syncthreads();

    __shared__ bool s_is_last;
    if (tid == 0) {
        float s = 0.0f;
#pragma unroll
        for (int w = 0; w < 8; w++) s += s_warp[w];
        g_partials[bm] = s;
        __threadfence();
        unsigned int prev = atomicAdd(&g_done, 1u);
        s_is_last = (prev == NBLK - 1);
    }
    __syncthreads();

    // --- Last block reduces all partials (fixed order -> deterministic)
    if (s_is_last) {
        double dacc = 0.0;
#pragma unroll
        for (int k = 0; k < (NBLK + 255) / 256; k++) {
            int i = k * 256 + tid;
            if (i < NBLK) dacc += (double)g_partials[i];
        }
#pragma unroll
        for (int o = 16; o > 0; o >>= 1)
            dacc += __shfl_down_sync(0xffffffffu, dacc, o);

        __shared__ double s_dwarp[8];
        if (lane == 0) s_dwarp[wid] = dacc;
        __syncthreads();
        if (tid == 0) {
            double s = 0.0;
#pragma unroll
            for (int w = 0; w < 8; w++) s += s_dwarp[w];
            out[0] = (float)(0.01 * s / (double)NPAIR_DENOM);
            g_done = 0;                  // reset for next graph replay
        }
    }
}

extern "C" void kernel_launch(void* const* d_in, const int* in_sizes, int n_in,
                              void* d_out, int out_size)
{
    const float* features = (const float*)d_in[0];  // [B*T, H*W, D] f32
    const float* tracks   = (const float*)d_in[1];  // [B, T, M, 2]  f32
    const int*   vis      = (const int*)d_in[2];    // [B, T, M]     bool->int32
    float*       out      = (float*)d_out;

    gather_l1_fused_kernel<<<NBLK, 256>>>(features, tracks, vis, out);
}

// round 5
// speedup vs baseline: 1.2959x; 1.0173x over previous
#include <cuda_runtime.h>
#include <math.h>

// Problem constants (fixed by setup_inputs)
#define B_  2
#define T_  8
#define M_  900
#define H_  27
#define W_  27
#define D_  1024
#define PATCH_ 14

#define NBLK (B_ * M_)                    // 1800 blocks, one per (b, m)
#define NPAIR_DENOM (B_ * (T_ - 1) * M_)  // 12600, mean denominator

__device__ float        g_partials[NBLK];
__device__ unsigned int g_done = 0;   // reset by the last block each launch

__global__ __launch_bounds__(256, 6)     // 42-reg budget -> 6 blocks/SM, 2.03 waves
void gather_l1_fused_kernel(const float* __restrict__ features,
                            const float* __restrict__ tracks,
                            const int* __restrict__ vis,   // bool stored as int32
                            float* __restrict__ out)
{
    const int bm   = blockIdx.x;         // 0..1799
    const int b    = bm / M_;
    const int m    = bm - b * M_;
    const int tid  = threadIdx.x;        // 256 threads = 1024 floats / 4
    const int lane = tid & 31;
    const int wid  = tid >> 5;

    // --- Per-warp index computation: lanes 0..7 handle frame t=lane.
    // Same addresses in every warp -> L1 broadcast; no block barrier needed.
    int my_nn = 0, my_vis = 0;
    if (lane < T_) {
        const int t = lane;
        const float2 tr = *(const float2*)(tracks
            + (unsigned)(((b * T_ + t) * M_ + m) * 2));
        // nearest patch center c_j = 14j+7 -> j = clamp(floor(x/14), 0, 26)
        int j = (int)floorf(tr.x * (1.0f / PATCH_));
        int i = (int)floorf(tr.y * (1.0f / PATCH_));
        j = min(W_ - 1, max(0, j));
        i = min(H_ - 1, max(0, i));
        my_nn  = i * W_ + j;
        my_vis = vis[(unsigned)((b * T_ + t) * M_ + m)];
    }

    int nn[T_], vz[T_];
#pragma unroll
    for (int t = 0; t < T_; t++) {
        nn[t] = __shfl_sync(0xffffffffu, my_nn,  t);
        vz[t] = __shfl_sync(0xffffffffu, my_vis, t);
    }

    // --- Gather 8 rows; 8 independent LDG.128 per thread, 32-bit offsets.
    // Element offset: ((b*T+t)*729 + nn[t])*1024 + tid*4  < 2^26 -> fits u32.
    float4 pf[T_];
#pragma unroll
    for (int t = 0; t < T_; t++) {
        unsigned off = ((unsigned)((b * T_ + t) * (H_ * W_) + nn[t]) << 10)
                     + ((unsigned)tid << 2);
        pf[t] = *(const float4*)(features + off);
    }

    float acc = 0.0f;
#pragma unroll
    for (int t = 0; t < T_ - 1; t++) {
        float l1c = fabsf(pf[t].x - pf[t + 1].x)
                  + fabsf(pf[t].y - pf[t + 1].y)
                  + fabsf(pf[t].z - pf[t + 1].z)
                  + fabsf(pf[t].w - pf[t + 1].w);
        float l1r = fabsf(pf[0].x - pf[t + 1].x)
                  + fabsf(pf[0].y - pf[t + 1].y)
                  + fabsf(pf[0].z - pf[t + 1].z)
                  + fabsf(pf[0].w - pf[t + 1].w);
        if (vz[t] && vz[t + 1]) acc += l1c;
        if (vz[0] && vz[t + 1]) acc += l1r;
    }

    // --- Block reduction: warp shuffle, then 8 warp sums via shared
#pragma unroll
    for (int o = 16; o > 0; o >>= 1)
        acc += __shfl_down_sync(0xffffffffu, acc, o);

    __shared__ float s_warp[8];
    if (lane == 0) s_warp[wid] = acc;
    __syncthreads();

    __shared__ bool s_is_last;
    if (tid == 0) {
        float s = 0.0f;
#pragma unroll
        for (int w = 0; w < 8; w++) s += s_warp[w];
        g_partials[bm] = s;
        __threadfence();
        unsigned int prev = atomicAdd(&g_done, 1u);
        s_is_last = (prev == NBLK - 1);
    }
    __syncthreads();

    // --- Last block reduces all partials (fixed order -> deterministic)
    if (s_is_last) {
        double dacc = 0.0;
#pragma unroll
        for (int k = 0; k < (NBLK + 255) / 256; k++) {
            int i = k * 256 + tid;
            if (i < NBLK) dacc += (double)g_partials[i];
        }
#pragma unroll
        for (int o = 16; o > 0; o >>= 1)
            dacc += __shfl_down_sync(0xffffffffu, dacc, o);

        __shared__ double s_dwarp[8];
        if (lane == 0) s_dwarp[wid] = dacc;
        __syncthreads();
        if (tid == 0) {
            double s = 0.0;
#pragma unroll
            for (int w = 0; w < 8; w++) s += s_dwarp[w];
            out[0] = (float)(0.01 * s / (double)NPAIR_DENOM);
            g_done = 0;                  // reset for next graph replay
        }
    }
}

extern "C" void kernel_launch(void* const* d_in, const int* in_sizes, int n_in,
                              void* d_out, int out_size)
{
    const float* features = (const float*)d_in[0];  // [B*T, H*W, D] f32
    const float* tracks   = (const float*)d_in[1];  // [B, T, M, 2]  f32
    const int*   vis      = (const int*)d_in[2];    // [B, T, M]     bool->int32
    float*       out      = (float*)d_out;

    gather_l1_fused_kernel<<<NBLK, 256>>>(features, tracks, vis, out);
}

// round 6
// speedup vs baseline: 1.2987x; 1.0022x over previous
#include <cuda_runtime.h>
#include <math.h>

// Problem constants (fixed by setup_inputs)
#define B_  2
#define T_  8
#define M_  900
#define H_  27
#define W_  27
#define D_  1024
#define PATCH_ 14

#define NBLK (B_ * M_)                    // 1800 blocks, one per (b, m)
#define NPAIR_DENOM (B_ * (T_ - 1) * M_)  // 12600, mean denominator

__device__ float        g_partials[NBLK];
__device__ unsigned int g_done = 0;   // reset by the last block each launch

// L1 over 4 dims: 4 FADD (diffs) + 3 FADD (abs-modifier tree) = 7 issued ops
__device__ __forceinline__ float l1_4(const float4& a, const float4& b)
{
    float d0 = a.x - b.x;
    float d1 = a.y - b.y;
    float d2 = a.z - b.z;
    float d3 = a.w - b.w;
    return (fabsf(d0) + fabsf(d1)) + (fabsf(d2) + fabsf(d3));
}

__global__ __launch_bounds__(256, 6)
void gather_l1_fused_kernel(const float* __restrict__ features,
                            const float* __restrict__ tracks,
                            const int* __restrict__ vis,   // bool stored as int32
                            float* __restrict__ out)
{
    const int bm   = blockIdx.x;         // 0..1799
    const int b    = bm / M_;
    const int m    = bm - b * M_;
    const int tid  = threadIdx.x;        // 256 threads = 1024 floats / 4
    const int lane = tid & 31;
    const int wid  = tid >> 5;

    // --- Per-warp index computation: lanes 0..7 handle frame t=lane.
    // Same addresses in every warp -> L1 broadcast; no block barrier needed.
    int my_nn = 0, my_vis = 0;
    if (lane < T_) {
        const int t = lane;
        const float2 tr = *(const float2*)(tracks
            + (unsigned)(((b * T_ + t) * M_ + m) * 2));
        // nearest patch center c_j = 14j+7 -> j = clamp(floor(x/14), 0, 26)
        int j = (int)floorf(tr.x * (1.0f / PATCH_));
        int i = (int)floorf(tr.y * (1.0f / PATCH_));
        j = min(W_ - 1, max(0, j));
        i = min(H_ - 1, max(0, i));
        my_nn  = i * W_ + j;
        my_vis = vis[(unsigned)((b * T_ + t) * M_ + m)];
    }

    int nn[T_];
    float fv[T_];                         // visibility as float 0/1
#pragma unroll
    for (int t = 0; t < T_; t++) {
        nn[t] = __shfl_sync(0xffffffffu, my_nn, t);
        fv[t] = (float)__shfl_sync(0xffffffffu, my_vis, t);
    }

    // --- Gather 8 rows; 8 independent LDG.128 per thread, 32-bit offsets.
    float4 pf[T_];
#pragma unroll
    for (int t = 0; t < T_; t++) {
        unsigned off = ((unsigned)((b * T_ + t) * (H_ * W_) + nn[t]) << 10)
                     + ((unsigned)tid << 2);
        pf[t] = *(const float4*)(features + off);
    }

    // --- 13 distinct pairs; pair (0,1) serves both consec and ref terms.
    // acc = sum over consec pairs (t,t+1) masked by fv[t]*fv[t+1]
    //     + sum over ref    pairs (0,t+1) masked by fv[0]*fv[t+1]
    float l01 = l1_4(pf[0], pf[1]);
    float m01 = fv[0] * fv[1];
    float acc_c = m01 * l01;              // consec pair t=0
    float acc_r = m01 * l01;              // ref pair t=0 (same pair)
#pragma unroll
    for (int t = 1; t < T_ - 1; t++) {
        float lc = l1_4(pf[t], pf[t + 1]);
        float lr = l1_4(pf[0], pf[t + 1]);
        acc_c = fmaf(fv[t] * fv[t + 1], lc, acc_c);
        acc_r = fmaf(fv[0] * fv[t + 1], lr, acc_r);
    }
    float acc = acc_c + acc_r;

    // --- Block reduction: warp shuffle, then 8 warp sums via shared
#pragma unroll
    for (int o = 16; o > 0; o >>= 1)
        acc += __shfl_down_sync(0xffffffffu, acc, o);

    __shared__ float s_warp[8];
    if (lane == 0) s_warp[wid] = acc;
    __syncthreads();

    __shared__ bool s_is_last;
    if (tid == 0) {
        float s = 0.0f;
#pragma unroll
        for (int w = 0; w < 8; w++) s += s_warp[w];
        g_partials[bm] = s;
        __threadfence();
        unsigned int prev = atomicAdd(&g_done, 1u);
        s_is_last = (prev == NBLK - 1);
    }
    __syncthreads();

    // --- Last block reduces all partials (fixed order -> deterministic)
    if (s_is_last) {
        double dacc = 0.0;
#pragma unroll
        for (int k = 0; k < (NBLK + 255) / 256; k++) {
            int i = k * 256 + tid;
            if (i < NBLK) dacc += (double)g_partials[i];
        }
#pragma unroll
        for (int o = 16; o > 0; o >>= 1)
            dacc += __shfl_down_sync(0xffffffffu, dacc, o);

        __shared__ double s_dwarp[8];
        if (lane == 0) s_dwarp[wid] = dacc;
        __syncthreads();
        if (tid == 0) {
            double s = 0.0;
#pragma unroll
            for (int w = 0; w < 8; w++) s += s_dwarp[w];
            out[0] = (float)(0.01 * s / (double)NPAIR_DENOM);
            g_done = 0;                  // reset for next graph replay
        }
    }
}

extern "C" void kernel_launch(void* const* d_in, const int* in_sizes, int n_in,
                              void* d_out, int out_size)
{
    const float* features = (const float*)d_in[0];  // [B*T, H*W, D] f32
    const float* tracks   = (const float*)d_in[1];  // [B, T, M, 2]  f32
    const int*   vis      = (const int*)d_in[2];    // [B, T, M]     bool->int32
    float*       out      = (float*)d_out;

    gather_l1_fused_kernel<<<NBLK, 256>>>(features, tracks, vis, out);
}